// round 1
// baseline (speedup 1.0000x reference)
#include <cuda_runtime.h>
#include <math.h>

#define EPS 1e-5f

// ---------------- persistent scratch (no allocs allowed) ----------------
__device__ float g_layout[64 * 5 * 108 * 108];   // NCHW after transpose
__device__ float g_y1[64 * 32 * 52 * 52];        // conv1 raw out
__device__ float g_y2[64 * 64 * 24 * 24];        // conv2 raw out
__device__ float g_y2n[64 * 64 * 24 * 24];       // BN2+leaky applied
__device__ float g_fc1[64 * 512];                // fc1 accumulator (split-K atomics)
__device__ float g_s1[32], g_sh1[32];
__device__ float g_s2[64], g_sh2[64];
__device__ float g_s3[512], g_sh3[512];

// ---------------- f32x2 packed helpers ----------------
__device__ __forceinline__ unsigned long long fma2(unsigned long long a,
                                                   unsigned long long b,
                                                   unsigned long long c) {
    unsigned long long d;
    asm("fma.rn.f32x2 %0, %1, %2, %3;" : "=l"(d) : "l"(a), "l"(b), "l"(c));
    return d;
}
__device__ __forceinline__ unsigned long long pk2(float a, float b) {
    unsigned long long r;
    asm("mov.b64 %0, {%1, %2};" : "=l"(r) : "f"(a), "f"(b));
    return r;
}
__device__ __forceinline__ void upk2(unsigned long long v, float& a, float& b) {
    asm("mov.b64 {%0, %1}, %2;" : "=f"(a), "=f"(b) : "l"(v));
}
__device__ __forceinline__ float leaky(float v) { return v > 0.f ? v : 0.2f * v; }

// ---------------- K0: zero fc1 accumulator ----------------
__global__ void zero_fc1_kernel() {
    g_fc1[blockIdx.x * 256 + threadIdx.x] = 0.f;   // <<<128,256>>> covers 32768
}

// ---------------- K1: layout render ----------------
// grid (46, 64), block 256. Per pixel: max over 9 objects of xy_max * cls.
__global__ void layout_kernel(const float* __restrict__ img) {
    int b = blockIdx.y, t = threadIdx.x;
    __shared__ float so[81];
    if (t < 81) so[t] = img[b * 81 + t];
    __syncthreads();
    int p = blockIdx.x * 256 + t;
    if (p >= 11664) return;
    int y = p / 108, x = p - y * 108;
    float fx = (float)x, fy = (float)y;
    float m[5];
#pragma unroll
    for (int c = 0; c < 5; c++) m[c] = -3.4e38f;
#pragma unroll
    for (int o = 0; o < 9; o++) {
        const float* f = &so[o * 9];
        float xc = f[0] * 108.f, yc = f[1] * 108.f;
        float hw = f[2] * 54.f, hh = f[3] * 54.f;
        float x1 = xc - hw, x2 = xc + hw, y1 = yc - hh, y2 = yc + hh;
        float x1d = fx - x1, x2d = x2 - fx, y1d = fy - y1, y2d = y2 - fy;
        float yin = __saturatef(y1d) * __saturatef(y2d);
        float xin = __saturatef(x1d) * __saturatef(x2d);
        float l1 = fmaxf(1.f - fabsf(x1d), 0.f) * yin;
        float l2 = fmaxf(1.f - fabsf(x2d), 0.f) * yin;
        float l3 = fmaxf(1.f - fabsf(y1d), 0.f) * xin;
        float l4 = fmaxf(1.f - fabsf(y2d), 0.f) * xin;
        float xym = fmaxf(fmaxf(l1, l2), fmaxf(l3, l4));
#pragma unroll
        for (int c = 0; c < 5; c++) m[c] = fmaxf(m[c], xym * f[4 + c]);
    }
#pragma unroll
    for (int c = 0; c < 5; c++) g_layout[(b * 5 + c) * 11664 + p] = m[c];
}

// ---------------- K2: conv1 (5->32, 5x5, s2), bias skipped (BN cancels) ----------
// grid (13 row-tiles, 64 b), block 128. Thread: 2 pixels (x2, x2+26), 32 oc as 16 f32x2.
__global__ void conv1_kernel(const float* __restrict__ w1) {
    __shared__ __align__(16) float sW[4000];        // [k=125][oc=32] transposed
    __shared__ float sIn[5 * 11 * 108];             // 5 ch x 11 rows x 108
    int b = blockIdx.y, tile = blockIdx.x, t = threadIdx.x;
    for (int i = t; i < 4000; i += 128) {
        int oc = i / 125, k = i - oc * 125;
        sW[k * 32 + oc] = w1[i];
    }
    int r0 = 8 * tile;
    for (int i = t; i < 5940; i += 128) {
        int ic = i / 1188, rem = i - ic * 1188;
        int row = rem / 108, col = rem - row * 108;
        sIn[i] = g_layout[(b * 5 + ic) * 11664 + (r0 + row) * 108 + col];
    }
    __syncthreads();
    if (t >= 104) return;
    int x2 = t % 26, yy = t / 26;
    unsigned long long a0[16], a1[16];
#pragma unroll
    for (int p = 0; p < 16; p++) { a0[p] = 0ULL; a1[p] = 0ULL; }
    for (int ic = 0; ic < 5; ic++)
        for (int ky = 0; ky < 5; ky++) {
            int base = ic * 1188 + (2 * yy + ky) * 108 + 2 * x2;
            int kb = ic * 25 + ky * 5;
#pragma unroll
            for (int kx = 0; kx < 5; kx++) {
                float v0 = sIn[base + kx], v1 = sIn[base + 52 + kx];
                unsigned long long p0 = pk2(v0, v0), p1 = pk2(v1, v1);
                const unsigned long long* wr =
                    (const unsigned long long*)&sW[(kb + kx) * 32];
#pragma unroll
                for (int p = 0; p < 16; p++) {
                    unsigned long long w = wr[p];
                    a0[p] = fma2(p0, w, a0[p]);
                    a1[p] = fma2(p1, w, a1[p]);
                }
            }
        }
    int y = 4 * tile + yy;
#pragma unroll
    for (int p = 0; p < 16; p++) {
        float l, h;
        upk2(a0[p], l, h);
        g_y1[((b * 32 + 2 * p) * 52 + y) * 52 + x2] = l;
        g_y1[((b * 32 + 2 * p + 1) * 52 + y) * 52 + x2] = h;
        upk2(a1[p], l, h);
        g_y1[((b * 32 + 2 * p) * 52 + y) * 52 + x2 + 26] = l;
        g_y1[((b * 32 + 2 * p + 1) * 52 + y) * 52 + x2 + 26] = h;
    }
}

// ---------------- stats: per-channel mean/var -> scale/shift (one block/ch) -----
__global__ void stats_kernel(int which, const float* __restrict__ gamma,
                             const float* __restrict__ beta) {
    const float* src = which ? g_y2 : g_y1;
    int hw = which ? 576 : 2704;
    int nch = which ? 64 : 32;
    float* scale = which ? g_s2 : g_s1;
    float* shift = which ? g_sh2 : g_sh1;
    int c = blockIdx.x, t = threadIdx.x;
    double s1 = 0.0, s2 = 0.0;
    for (int b = 0; b < 64; b++) {
        const float* pc = src + (size_t)(b * nch + c) * hw;
        for (int s = t; s < hw; s += 256) {
            float v = pc[s];
            s1 += v;
            s2 += (double)v * v;
        }
    }
    __shared__ double r1[256], r2[256];
    r1[t] = s1; r2[t] = s2;
    __syncthreads();
    for (int o = 128; o > 0; o >>= 1) {
        if (t < o) { r1[t] += r1[t + o]; r2[t] += r2[t + o]; }
        __syncthreads();
    }
    if (t == 0) {
        double N = 64.0 * hw;
        double m = r1[0] / N;
        double var = r2[0] / N - m * m;
        float sc = gamma[c] * (float)(1.0 / sqrt(var + (double)EPS));
        scale[c] = sc;
        shift[c] = beta[c] - (float)m * sc;
    }
}

// ---------------- K4: conv2 (32->64, 5x5, s2), BN1+leaky fused into input load ----
// grid (4 oc-groups of 16, 64 b), block 288 (= 24 rows x 12 x-positions, 2 px each).
__global__ void conv2_kernel(const float* __restrict__ w2) {
    __shared__ float sIn[51 * 52];
    __shared__ __align__(16) float sWt[400];        // [kk=25][oc=16]
    int ocg = blockIdx.x, b = blockIdx.y, t = threadIdx.x;
    int x = t % 12, y = t / 12;
    unsigned long long a0[8], a1[8];
#pragma unroll
    for (int p = 0; p < 8; p++) { a0[p] = 0ULL; a1[p] = 0ULL; }
    for (int ic = 0; ic < 32; ic++) {
        float s1c = g_s1[ic], sh1c = g_sh1[ic];
        __syncthreads();
        for (int i = t; i < 2652; i += 288) {
            int row = i / 52, col = i - row * 52;
            float v = 0.f;
            if (col < 51) {
                float raw = g_y1[((b * 32 + ic) * 52 + row) * 52 + col];
                v = leaky(fmaf(raw, s1c, sh1c));
            }
            sIn[i] = v;
        }
        for (int i = t; i < 400; i += 288) {
            int o = i & 15, kk = i >> 4;
            sWt[i] = w2[((ocg * 16 + o) * 32 + ic) * 25 + kk];
        }
        __syncthreads();
#pragma unroll
        for (int ky = 0; ky < 5; ky++) {
            int rb = (2 * y + ky) * 52 + 2 * x;
#pragma unroll
            for (int kx = 0; kx < 5; kx++) {
                float v0 = sIn[rb + kx], v1 = sIn[rb + 24 + kx];
                unsigned long long p0 = pk2(v0, v0), p1 = pk2(v1, v1);
                const unsigned long long* wr =
                    (const unsigned long long*)&sWt[(ky * 5 + kx) * 16];
#pragma unroll
                for (int p = 0; p < 8; p++) {
                    unsigned long long w = wr[p];
                    a0[p] = fma2(p0, w, a0[p]);
                    a1[p] = fma2(p1, w, a1[p]);
                }
            }
        }
    }
#pragma unroll
    for (int p = 0; p < 8; p++) {
        int oc = ocg * 16 + 2 * p;
        float l, h;
        upk2(a0[p], l, h);
        g_y2[(b * 64 + oc) * 576 + y * 24 + x] = l;
        g_y2[(b * 64 + oc + 1) * 576 + y * 24 + x] = h;
        upk2(a1[p], l, h);
        g_y2[(b * 64 + oc) * 576 + y * 24 + x + 12] = l;
        g_y2[(b * 64 + oc + 1) * 576 + y * 24 + x + 12] = h;
    }
}

// ---------------- K5b: apply BN2 + leaky ----------------
__global__ void apply2_kernel() {
    int i = blockIdx.x * 256 + threadIdx.x;
    if (i >= 64 * 64 * 576) return;
    int c = (i / 576) & 63;
    g_y2n[i] = leaky(fmaf(g_y2[i], g_s2[c], g_sh2[c]));
}

// ---------------- K6: fc1 GEMM, split-K, atomic accumulate ----------------
// C[64,512] = X[64,36864] * W^T. grid (4 n-tiles of 128, 36 k-splits of 1024), 256 thr.
// Thread tile: 8 b (as 4 f32x2 pairs) x 4 j (j = c + 32*jj, conflict-free).
__global__ void fc1_kernel(const float* __restrict__ W) {
    __shared__ __align__(16) float sX[32 * 64];
    __shared__ __align__(16) float sW[32 * 128];
    int n0 = blockIdx.x * 128, k0 = blockIdx.y * 1024, t = threadIdx.x;
    int bgrp = t >> 5, c = t & 31;
    int b0 = bgrp * 8;
    unsigned long long acc[4][4];
#pragma unroll
    for (int i = 0; i < 4; i++)
#pragma unroll
        for (int j = 0; j < 4; j++) acc[i][j] = 0ULL;

    int xb = t >> 2, xks = (t & 3) * 8;     // X loader: batch xb, 8 consecutive k
    int wj = t >> 1, wks = (t & 1) * 16;    // W loader: row wj, 16 consecutive k

    for (int kt = 0; kt < 32; kt++) {
        int kb = k0 + kt * 32;
        __syncthreads();
        {
            const float4* src = (const float4*)&g_y2n[xb * 36864 + kb + xks];
            float4 q0 = src[0], q1 = src[1];
            float tmp[8] = {q0.x, q0.y, q0.z, q0.w, q1.x, q1.y, q1.z, q1.w};
#pragma unroll
            for (int i = 0; i < 8; i++) sX[(xks + i) * 64 + xb] = tmp[i];
        }
        {
            const float4* src =
                (const float4*)&W[(size_t)(n0 + wj) * 36864 + kb + wks];
            float4 q0 = src[0], q1 = src[1], q2 = src[2], q3 = src[3];
            float tmp[16] = {q0.x, q0.y, q0.z, q0.w, q1.x, q1.y, q1.z, q1.w,
                             q2.x, q2.y, q2.z, q2.w, q3.x, q3.y, q3.z, q3.w};
#pragma unroll
            for (int i = 0; i < 16; i++) sW[(wks + i) * 128 + wj] = tmp[i];
        }
        __syncthreads();
#pragma unroll 4
        for (int kk = 0; kk < 32; kk++) {
            unsigned long long xp[4];
            const unsigned long long* xr =
                (const unsigned long long*)&sX[kk * 64 + b0];
#pragma unroll
            for (int bp = 0; bp < 4; bp++) xp[bp] = xr[bp];
#pragma unroll
            for (int j = 0; j < 4; j++) {
                float w = sW[kk * 128 + c + 32 * j];
                unsigned long long wp = pk2(w, w);
#pragma unroll
                for (int bp = 0; bp < 4; bp++)
                    acc[bp][j] = fma2(xp[bp], wp, acc[bp][j]);
            }
        }
    }
#pragma unroll
    for (int bp = 0; bp < 4; bp++)
#pragma unroll
        for (int j = 0; j < 4; j++) {
            float l, h;
            upk2(acc[bp][j], l, h);
            int jj = n0 + c + 32 * j;
            atomicAdd(&g_fc1[(b0 + 2 * bp) * 512 + jj], l);
            atomicAdd(&g_fc1[(b0 + 2 * bp + 1) * 512 + jj], h);
        }
}

// ---------------- K7: BN3 stats over batch (fc1 bias cancels) ----------------
__global__ void bn3_kernel(const float* __restrict__ g3, const float* __restrict__ b3) {
    int j = threadIdx.x;   // <<<1,512>>>
    double s1 = 0.0, s2 = 0.0;
    for (int b = 0; b < 64; b++) {
        float v = g_fc1[b * 512 + j];
        s1 += v;
        s2 += (double)v * v;
    }
    double m = s1 / 64.0, var = s2 / 64.0 - m * m;
    float sc = g3[j] * (float)(1.0 / sqrt(var + (double)EPS));
    g_s3[j] = sc;
    g_sh3[j] = b3[j] - (float)m * sc;
}

// ---------------- K8: BN3+leaky+fc2+sigmoid ----------------
__global__ void final_kernel(const float* __restrict__ w2, const float* __restrict__ b2,
                             float* __restrict__ out) {
    int b = blockIdx.x, t = threadIdx.x;   // <<<64,256>>>
    float s = 0.f;
    for (int j = t; j < 512; j += 256) {
        float v = leaky(fmaf(g_fc1[b * 512 + j], g_s3[j], g_sh3[j]));
        s += v * w2[j];
    }
    __shared__ float red[256];
    red[t] = s;
    __syncthreads();
    for (int o = 128; o > 0; o >>= 1) {
        if (t < o) red[t] += red[t + o];
        __syncthreads();
    }
    if (t == 0) {
        float z = red[0] + b2[0];
        out[b] = 1.f / (1.f + expf(-z));
    }
}

// ---------------- launch ----------------
extern "C" void kernel_launch(void* const* d_in, const int* in_sizes, int n_in,
                              void* d_out, int out_size) {
    const float* image   = (const float*)d_in[0];
    const float* conv1_w = (const float*)d_in[1];
    const float* bn1_g   = (const float*)d_in[3];
    const float* bn1_b   = (const float*)d_in[4];
    const float* conv2_w = (const float*)d_in[5];
    const float* bn2_g   = (const float*)d_in[7];
    const float* bn2_b   = (const float*)d_in[8];
    const float* fc1_w   = (const float*)d_in[9];
    const float* bn3_g   = (const float*)d_in[11];
    const float* bn3_b   = (const float*)d_in[12];
    const float* fc2_w   = (const float*)d_in[13];
    const float* fc2_b   = (const float*)d_in[14];
    float* out = (float*)d_out;

    zero_fc1_kernel<<<128, 256>>>();
    layout_kernel<<<dim3(46, 64), 256>>>(image);
    conv1_kernel<<<dim3(13, 64), 128>>>(conv1_w);
    stats_kernel<<<32, 256>>>(0, bn1_g, bn1_b);
    conv2_kernel<<<dim3(4, 64), 288>>>(conv2_w);
    stats_kernel<<<64, 256>>>(1, bn2_g, bn2_b);
    apply2_kernel<<<9216, 256>>>();
    fc1_kernel<<<dim3(4, 36), 256>>>(fc1_w);
    bn3_kernel<<<1, 512>>>(bn3_g, bn3_b);
    final_kernel<<<64, 256>>>(fc2_w, fc2_b, out);
}

// round 2
// speedup vs baseline: 1.5426x; 1.5426x over previous
#include <cuda_runtime.h>
#include <math.h>

#define EPS 1e-5f

// ---------------- persistent scratch (no allocs allowed) ----------------
__device__ float g_layout[64 * 5 * 108 * 108];   // NCHW after transpose
__device__ float g_y1[64 * 32 * 52 * 52];        // conv1 raw out
__device__ float g_y2[64 * 64 * 24 * 24];        // conv2 raw out
__device__ float g_fc1[64 * 512];                // fc1 accumulator (split-K atomics)
__device__ float g_s1[32], g_sh1[32];
__device__ float g_s2[64], g_sh2[64];
__device__ float g_s3[512], g_sh3[512];
__device__ double g_sum[64], g_sumsq[64];        // stats partials (max nch = 64)

// ---------------- f32x2 packed helpers ----------------
__device__ __forceinline__ unsigned long long fma2(unsigned long long a,
                                                   unsigned long long b,
                                                   unsigned long long c) {
    unsigned long long d;
    asm("fma.rn.f32x2 %0, %1, %2, %3;" : "=l"(d) : "l"(a), "l"(b), "l"(c));
    return d;
}
__device__ __forceinline__ unsigned long long pk2(float a, float b) {
    unsigned long long r;
    asm("mov.b64 %0, {%1, %2};" : "=l"(r) : "f"(a), "f"(b));
    return r;
}
__device__ __forceinline__ void upk2(unsigned long long v, float& a, float& b) {
    asm("mov.b64 {%0, %1}, %2;" : "=f"(a), "=f"(b) : "l"(v));
}
__device__ __forceinline__ float leaky(float v) { return v > 0.f ? v : 0.2f * v; }

// ---------------- K0: zero fc1 accumulator ----------------
__global__ void zero_fc1_kernel() {
    g_fc1[blockIdx.x * 256 + threadIdx.x] = 0.f;   // <<<128,256>>> covers 32768
}

__global__ void zero_stats_kernel() {
    int t = threadIdx.x;                            // <<<1,64>>>
    if (t < 64) { g_sum[t] = 0.0; g_sumsq[t] = 0.0; }
}

// ---------------- K1: layout render ----------------
// grid (46, 64), block 256. Per pixel: max over 9 objects of xy_max * cls.
__global__ void layout_kernel(const float* __restrict__ img) {
    int b = blockIdx.y, t = threadIdx.x;
    __shared__ float so[81];
    if (t < 81) so[t] = img[b * 81 + t];
    __syncthreads();
    int p = blockIdx.x * 256 + t;
    if (p >= 11664) return;
    int y = p / 108, x = p - y * 108;
    float fx = (float)x, fy = (float)y;
    float m[5];
#pragma unroll
    for (int c = 0; c < 5; c++) m[c] = -3.4e38f;
#pragma unroll
    for (int o = 0; o < 9; o++) {
        const float* f = &so[o * 9];
        float xc = f[0] * 108.f, yc = f[1] * 108.f;
        float hw = f[2] * 54.f, hh = f[3] * 54.f;
        float x1 = xc - hw, x2 = xc + hw, y1 = yc - hh, y2 = yc + hh;
        float x1d = fx - x1, x2d = x2 - fx, y1d = fy - y1, y2d = y2 - fy;
        float yin = __saturatef(y1d) * __saturatef(y2d);
        float xin = __saturatef(x1d) * __saturatef(x2d);
        float l1 = fmaxf(1.f - fabsf(x1d), 0.f) * yin;
        float l2 = fmaxf(1.f - fabsf(x2d), 0.f) * yin;
        float l3 = fmaxf(1.f - fabsf(y1d), 0.f) * xin;
        float l4 = fmaxf(1.f - fabsf(y2d), 0.f) * xin;
        float xym = fmaxf(fmaxf(l1, l2), fmaxf(l3, l4));
#pragma unroll
        for (int c = 0; c < 5; c++) m[c] = fmaxf(m[c], xym * f[4 + c]);
    }
#pragma unroll
    for (int c = 0; c < 5; c++) g_layout[(b * 5 + c) * 11664 + p] = m[c];
}

// ---------------- K2: conv1 (5->32, 5x5, s2), bias skipped (BN cancels) ----------
// grid (13 row-tiles, 64 b), block 128. Thread: 2 pixels (x2, x2+26), 32 oc as 16 f32x2.
__global__ void conv1_kernel(const float* __restrict__ w1) {
    __shared__ __align__(16) float sW[4000];        // [k=125][oc=32] transposed
    __shared__ float sIn[5 * 11 * 108];             // 5 ch x 11 rows x 108
    int b = blockIdx.y, tile = blockIdx.x, t = threadIdx.x;
    for (int i = t; i < 4000; i += 128) {
        int oc = i / 125, k = i - oc * 125;
        sW[k * 32 + oc] = w1[i];
    }
    int r0 = 8 * tile;
    for (int i = t; i < 5940; i += 128) {
        int ic = i / 1188, rem = i - ic * 1188;
        int row = rem / 108, col = rem - row * 108;
        sIn[i] = g_layout[(b * 5 + ic) * 11664 + (r0 + row) * 108 + col];
    }
    __syncthreads();
    if (t >= 104) return;
    int x2 = t % 26, yy = t / 26;
    unsigned long long a0[16], a1[16];
#pragma unroll
    for (int p = 0; p < 16; p++) { a0[p] = 0ULL; a1[p] = 0ULL; }
    for (int ic = 0; ic < 5; ic++)
        for (int ky = 0; ky < 5; ky++) {
            int base = ic * 1188 + (2 * yy + ky) * 108 + 2 * x2;
            int kb = ic * 25 + ky * 5;
#pragma unroll
            for (int kx = 0; kx < 5; kx++) {
                float v0 = sIn[base + kx], v1 = sIn[base + 52 + kx];
                unsigned long long p0 = pk2(v0, v0), p1 = pk2(v1, v1);
                const unsigned long long* wr =
                    (const unsigned long long*)&sW[(kb + kx) * 32];
#pragma unroll
                for (int p = 0; p < 16; p++) {
                    unsigned long long w = wr[p];
                    a0[p] = fma2(p0, w, a0[p]);
                    a1[p] = fma2(p1, w, a1[p]);
                }
            }
        }
    int y = 4 * tile + yy;
#pragma unroll
    for (int p = 0; p < 16; p++) {
        float l, h;
        upk2(a0[p], l, h);
        g_y1[((b * 32 + 2 * p) * 52 + y) * 52 + x2] = l;
        g_y1[((b * 32 + 2 * p + 1) * 52 + y) * 52 + x2] = h;
        upk2(a1[p], l, h);
        g_y1[((b * 32 + 2 * p) * 52 + y) * 52 + x2 + 26] = l;
        g_y1[((b * 32 + 2 * p + 1) * 52 + y) * 52 + x2 + 26] = h;
    }
}

// ---------------- stats stage 1: per-(channel, batch-group) partial sums --------
// grid (nch, 16): each block does 4 batches of one channel. fp32 per-thread
// partials (<=44 values), double block-reduce, double atomics to globals.
__global__ void stats_partial_kernel(int which) {
    const float* src = which ? g_y2 : g_y1;
    int hw = which ? 576 : 2704;
    int nch = which ? 64 : 32;
    int c = blockIdx.x, bg = blockIdx.y, t = threadIdx.x;
    double d1 = 0.0, d2 = 0.0;
#pragma unroll
    for (int bb = 0; bb < 4; bb++) {
        int b = bg * 4 + bb;
        const float* pc = src + (size_t)(b * nch + c) * hw;
        float l1 = 0.f, l2 = 0.f;
        for (int s = t; s < hw; s += 256) {
            float v = pc[s];
            l1 += v;
            l2 = fmaf(v, v, l2);
        }
        d1 += (double)l1;
        d2 += (double)l2;
    }
    __shared__ double r1[256], r2[256];
    r1[t] = d1; r2[t] = d2;
    __syncthreads();
    for (int o = 128; o > 0; o >>= 1) {
        if (t < o) { r1[t] += r1[t + o]; r2[t] += r2[t + o]; }
        __syncthreads();
    }
    if (t == 0) {
        atomicAdd(&g_sum[c], r1[0]);
        atomicAdd(&g_sumsq[c], r2[0]);
    }
}

// ---------------- stats stage 2: finalize scale/shift ----------------
__global__ void stats_final_kernel(int which, const float* __restrict__ gamma,
                                   const float* __restrict__ beta) {
    int hw = which ? 576 : 2704;
    int nch = which ? 64 : 32;
    float* scale = which ? g_s2 : g_s1;
    float* shift = which ? g_sh2 : g_sh1;
    int c = threadIdx.x;                            // <<<1,64>>>
    if (c >= nch) return;
    double N = 64.0 * hw;
    double m = g_sum[c] / N;
    double var = g_sumsq[c] / N - m * m;
    float sc = gamma[c] * (float)(1.0 / sqrt(var + (double)EPS));
    scale[c] = sc;
    shift[c] = beta[c] - (float)m * sc;
}

// ---------------- K4: conv2 (32->64, 5x5, s2), BN1+leaky fused into input load ----
// grid (4 oc-groups of 16, 64 b), block 288 (= 24 rows x 12 x-positions, 2 px each).
__global__ void conv2_kernel(const float* __restrict__ w2) {
    __shared__ float sIn[51 * 52];
    __shared__ __align__(16) float sWt[400];        // [kk=25][oc=16]
    int ocg = blockIdx.x, b = blockIdx.y, t = threadIdx.x;
    int x = t % 12, y = t / 12;
    unsigned long long a0[8], a1[8];
#pragma unroll
    for (int p = 0; p < 8; p++) { a0[p] = 0ULL; a1[p] = 0ULL; }
    for (int ic = 0; ic < 32; ic++) {
        float s1c = g_s1[ic], sh1c = g_sh1[ic];
        __syncthreads();
        for (int i = t; i < 2652; i += 288) {
            int row = i / 52, col = i - row * 52;
            float v = 0.f;
            if (col < 51) {
                float raw = g_y1[((b * 32 + ic) * 52 + row) * 52 + col];
                v = leaky(fmaf(raw, s1c, sh1c));
            }
            sIn[i] = v;
        }
        for (int i = t; i < 400; i += 288) {
            int o = i & 15, kk = i >> 4;
            sWt[i] = w2[((ocg * 16 + o) * 32 + ic) * 25 + kk];
        }
        __syncthreads();
#pragma unroll
        for (int ky = 0; ky < 5; ky++) {
            int rb = (2 * y + ky) * 52 + 2 * x;
#pragma unroll
            for (int kx = 0; kx < 5; kx++) {
                float v0 = sIn[rb + kx], v1 = sIn[rb + 24 + kx];
                unsigned long long p0 = pk2(v0, v0), p1 = pk2(v1, v1);
                const unsigned long long* wr =
                    (const unsigned long long*)&sWt[(ky * 5 + kx) * 16];
#pragma unroll
                for (int p = 0; p < 8; p++) {
                    unsigned long long w = wr[p];
                    a0[p] = fma2(p0, w, a0[p]);
                    a1[p] = fma2(p1, w, a1[p]);
                }
            }
        }
    }
#pragma unroll
    for (int p = 0; p < 8; p++) {
        int oc = ocg * 16 + 2 * p;
        float l, h;
        upk2(a0[p], l, h);
        g_y2[(b * 64 + oc) * 576 + y * 24 + x] = l;
        g_y2[(b * 64 + oc + 1) * 576 + y * 24 + x] = h;
        upk2(a1[p], l, h);
        g_y2[(b * 64 + oc) * 576 + y * 24 + x + 12] = l;
        g_y2[(b * 64 + oc + 1) * 576 + y * 24 + x + 12] = h;
    }
}

// ---------------- K6: fc1 GEMM, split-K, atomic accumulate ----------------
// C[64,512] = act(bn2(y2)) [64,36864] * W^T. BN2+leaky fused into the X load
// (each 8-element k-group lies inside one channel: 576 % 8 == 0).
// grid (4 n-tiles of 128, 36 k-splits of 1024), 256 thr.
// Thread tile: 8 b (as 4 f32x2 pairs) x 4 j (j = c + 32*jj, conflict-free).
__global__ void fc1_kernel(const float* __restrict__ W) {
    __shared__ __align__(16) float sX[32 * 64];
    __shared__ __align__(16) float sW[32 * 128];
    int n0 = blockIdx.x * 128, k0 = blockIdx.y * 1024, t = threadIdx.x;
    int bgrp = t >> 5, c = t & 31;
    int b0 = bgrp * 8;
    unsigned long long acc[4][4];
#pragma unroll
    for (int i = 0; i < 4; i++)
#pragma unroll
        for (int j = 0; j < 4; j++) acc[i][j] = 0ULL;

    int xb = t >> 2, xks = (t & 3) * 8;     // X loader: batch xb, 8 consecutive k
    int wj = t >> 1, wks = (t & 1) * 16;    // W loader: row wj, 16 consecutive k

    for (int kt = 0; kt < 32; kt++) {
        int kb = k0 + kt * 32;
        __syncthreads();
        {
            int kidx = kb + xks;
            int ch = (kidx / 576) & 63;            // same channel for all 8 elems
            float sc = g_s2[ch], sh = g_sh2[ch];
            const float4* src = (const float4*)&g_y2[xb * 36864 + kidx];
            float4 q0 = src[0], q1 = src[1];
            float tmp[8] = {q0.x, q0.y, q0.z, q0.w, q1.x, q1.y, q1.z, q1.w};
#pragma unroll
            for (int i = 0; i < 8; i++)
                sX[(xks + i) * 64 + xb] = leaky(fmaf(tmp[i], sc, sh));
        }
        {
            const float4* src =
                (const float4*)&W[(size_t)(n0 + wj) * 36864 + kb + wks];
            float4 q0 = src[0], q1 = src[1], q2 = src[2], q3 = src[3];
            float tmp[16] = {q0.x, q0.y, q0.z, q0.w, q1.x, q1.y, q1.z, q1.w,
                             q2.x, q2.y, q2.z, q2.w, q3.x, q3.y, q3.z, q3.w};
#pragma unroll
            for (int i = 0; i < 16; i++) sW[(wks + i) * 128 + wj] = tmp[i];
        }
        __syncthreads();
#pragma unroll 4
        for (int kk = 0; kk < 32; kk++) {
            unsigned long long xp[4];
            const unsigned long long* xr =
                (const unsigned long long*)&sX[kk * 64 + b0];
#pragma unroll
            for (int bp = 0; bp < 4; bp++) xp[bp] = xr[bp];
#pragma unroll
            for (int j = 0; j < 4; j++) {
                float w = sW[kk * 128 + c + 32 * j];
                unsigned long long wp = pk2(w, w);
#pragma unroll
                for (int bp = 0; bp < 4; bp++)
                    acc[bp][j] = fma2(xp[bp], wp, acc[bp][j]);
            }
        }
    }
#pragma unroll
    for (int bp = 0; bp < 4; bp++)
#pragma unroll
        for (int j = 0; j < 4; j++) {
            float l, h;
            upk2(acc[bp][j], l, h);
            int jj = n0 + c + 32 * j;
            atomicAdd(&g_fc1[(b0 + 2 * bp) * 512 + jj], l);
            atomicAdd(&g_fc1[(b0 + 2 * bp + 1) * 512 + jj], h);
        }
}

// ---------------- K7: BN3 stats over batch (fc1 bias cancels) ----------------
__global__ void bn3_kernel(const float* __restrict__ g3, const float* __restrict__ b3) {
    int j = threadIdx.x;   // <<<1,512>>>
    float s1 = 0.f, s2 = 0.f;
#pragma unroll 8
    for (int b = 0; b < 64; b++) {
        float v = g_fc1[b * 512 + j];
        s1 += v;
        s2 = fmaf(v, v, s2);
    }
    double m = (double)s1 / 64.0, var = (double)s2 / 64.0 - m * m;
    float sc = g3[j] * (float)(1.0 / sqrt(var + (double)EPS));
    g_s3[j] = sc;
    g_sh3[j] = b3[j] - (float)m * sc;
}

// ---------------- K8: BN3+leaky+fc2+sigmoid ----------------
__global__ void final_kernel(const float* __restrict__ w2, const float* __restrict__ b2,
                             float* __restrict__ out) {
    int b = blockIdx.x, t = threadIdx.x;   // <<<64,256>>>
    float s = 0.f;
    for (int j = t; j < 512; j += 256) {
        float v = leaky(fmaf(g_fc1[b * 512 + j], g_s3[j], g_sh3[j]));
        s += v * w2[j];
    }
    __shared__ float red[256];
    red[t] = s;
    __syncthreads();
    for (int o = 128; o > 0; o >>= 1) {
        if (t < o) red[t] += red[t + o];
        __syncthreads();
    }
    if (t == 0) {
        float z = red[0] + b2[0];
        out[b] = 1.f / (1.f + expf(-z));
    }
}

// ---------------- launch ----------------
extern "C" void kernel_launch(void* const* d_in, const int* in_sizes, int n_in,
                              void* d_out, int out_size) {
    const float* image   = (const float*)d_in[0];
    const float* conv1_w = (const float*)d_in[1];
    const float* bn1_g   = (const float*)d_in[3];
    const float* bn1_b   = (const float*)d_in[4];
    const float* conv2_w = (const float*)d_in[5];
    const float* bn2_g   = (const float*)d_in[7];
    const float* bn2_b   = (const float*)d_in[8];
    const float* fc1_w   = (const float*)d_in[9];
    const float* bn3_g   = (const float*)d_in[11];
    const float* bn3_b   = (const float*)d_in[12];
    const float* fc2_w   = (const float*)d_in[13];
    const float* fc2_b   = (const float*)d_in[14];
    float* out = (float*)d_out;

    zero_fc1_kernel<<<128, 256>>>();
    layout_kernel<<<dim3(46, 64), 256>>>(image);
    conv1_kernel<<<dim3(13, 64), 128>>>(conv1_w);
    zero_stats_kernel<<<1, 64>>>();
    stats_partial_kernel<<<dim3(32, 16), 256>>>(0);
    stats_final_kernel<<<1, 64>>>(0, bn1_g, bn1_b);
    conv2_kernel<<<dim3(4, 64), 288>>>(conv2_w);
    zero_stats_kernel<<<1, 64>>>();
    stats_partial_kernel<<<dim3(64, 16), 256>>>(1);
    stats_final_kernel<<<1, 64>>>(1, bn2_g, bn2_b);
    fc1_kernel<<<dim3(4, 36), 256>>>(fc1_w);
    bn3_kernel<<<1, 512>>>(bn3_g, bn3_b);
    final_kernel<<<64, 256>>>(fc2_w, fc2_b, out);
}

// round 4
// speedup vs baseline: 2.0264x; 1.3136x over previous
#include <cuda_runtime.h>
#include <math.h>

#define EPS 1e-5f
typedef unsigned long long ull;

// ---------------- persistent scratch ----------------
__device__ float g_layout[64 * 5 * 108 * 108];
__device__ float g_y1[64 * 32 * 52 * 52];
__device__ float g_y2[64 * 64 * 24 * 24];
__device__ float g_fc1[64 * 512];
__device__ float g_s3[512], g_sh3[512];
__device__ double g_sum1[32], g_sq1[32];
__device__ double g_sum2[64], g_sq2[64];

// ---------------- f32x2 helpers ----------------
__device__ __forceinline__ ull fma2(ull a, ull b, ull c) {
    ull d;
    asm("fma.rn.f32x2 %0, %1, %2, %3;" : "=l"(d) : "l"(a), "l"(b), "l"(c));
    return d;
}
__device__ __forceinline__ ull pk2(float a, float b) {
    ull r;
    asm("mov.b64 %0, {%1, %2};" : "=l"(r) : "f"(a), "f"(b));
    return r;
}
__device__ __forceinline__ void upk2(ull v, float& a, float& b) {
    asm("mov.b64 {%0, %1}, %2;" : "=f"(a), "=f"(b) : "l"(v));
}
__device__ __forceinline__ float leaky(float v) { return v > 0.f ? v : 0.2f * v; }

// ---------------- K0: zero fc1 acc + stats partials ----------------
__global__ void zero_kernel() {
    int i = blockIdx.x * 256 + threadIdx.x;   // <<<128,256>>> = 32768
    g_fc1[i] = 0.f;
    if (blockIdx.x == 0) {
        int t = threadIdx.x;
        if (t < 32) { g_sum1[t] = 0.0; g_sq1[t] = 0.0; }
        else if (t < 96) { g_sum2[t - 32] = 0.0; g_sq2[t - 32] = 0.0; }
    }
}

// ---------------- K1: layout render ----------------
__global__ void layout_kernel(const float* __restrict__ img) {
    int b = blockIdx.y, t = threadIdx.x;
    __shared__ float so[81];
    if (t < 81) so[t] = img[b * 81 + t];
    __syncthreads();
    int p = blockIdx.x * 256 + t;
    if (p >= 11664) return;
    int y = p / 108, x = p - y * 108;
    float fx = (float)x, fy = (float)y;
    float m[5];
#pragma unroll
    for (int c = 0; c < 5; c++) m[c] = -3.4e38f;
#pragma unroll
    for (int o = 0; o < 9; o++) {
        const float* f = &so[o * 9];
        float xc = f[0] * 108.f, yc = f[1] * 108.f;
        float hw = f[2] * 54.f, hh = f[3] * 54.f;
        float x1 = xc - hw, x2 = xc + hw, y1 = yc - hh, y2 = yc + hh;
        float x1d = fx - x1, x2d = x2 - fx, y1d = fy - y1, y2d = y2 - fy;
        float yin = __saturatef(y1d) * __saturatef(y2d);
        float xin = __saturatef(x1d) * __saturatef(x2d);
        float l1 = fmaxf(1.f - fabsf(x1d), 0.f) * yin;
        float l2 = fmaxf(1.f - fabsf(x2d), 0.f) * yin;
        float l3 = fmaxf(1.f - fabsf(y1d), 0.f) * xin;
        float l4 = fmaxf(1.f - fabsf(y2d), 0.f) * xin;
        float xym = fmaxf(fmaxf(l1, l2), fmaxf(l3, l4));
#pragma unroll
        for (int c = 0; c < 5; c++) m[c] = fmaxf(m[c], xym * f[4 + c]);
    }
#pragma unroll
    for (int c = 0; c < 5; c++) g_layout[(b * 5 + c) * 11664 + p] = m[c];
}

// ---------------- K2: conv1 + fused BN1 raw stats ----------------
// grid (13, 64), block 128 (104 active). 2 px/thread, 32 oc as 16 f32x2.
__global__ void conv1_kernel(const float* __restrict__ w1) {
    __shared__ __align__(16) float sW[4000];
    __shared__ float sIn[5 * 11 * 108];
    __shared__ float sRed[4 * 64];
    int b = blockIdx.y, tile = blockIdx.x, t = threadIdx.x;
    for (int i = t; i < 4000; i += 128) {
        int oc = i / 125, k = i - oc * 125;
        sW[k * 32 + oc] = w1[i];
    }
    int r0 = 8 * tile;
    for (int i = t; i < 5940; i += 128) {
        int ic = i / 1188, rem = i - ic * 1188;
        int row = rem / 108, col = rem - row * 108;
        sIn[i] = g_layout[(b * 5 + ic) * 11664 + (r0 + row) * 108 + col];
    }
    __syncthreads();
    bool act = (t < 104);
    int x2 = t % 26, yy = t / 26;
    ull a0[16], a1[16];
#pragma unroll
    for (int p = 0; p < 16; p++) { a0[p] = 0ULL; a1[p] = 0ULL; }
    if (act) {
        for (int ic = 0; ic < 5; ic++)
            for (int ky = 0; ky < 5; ky++) {
                int base = ic * 1188 + (2 * yy + ky) * 108 + 2 * x2;
                int kb = ic * 25 + ky * 5;
#pragma unroll
                for (int kx = 0; kx < 5; kx++) {
                    float v0 = sIn[base + kx], v1 = sIn[base + 52 + kx];
                    ull p0 = pk2(v0, v0), p1 = pk2(v1, v1);
                    const ull* wr = (const ull*)&sW[(kb + kx) * 32];
#pragma unroll
                    for (int p = 0; p < 16; p++) {
                        ull w = wr[p];
                        a0[p] = fma2(p0, w, a0[p]);
                        a1[p] = fma2(p1, w, a1[p]);
                    }
                }
            }
    }
    int y = 4 * tile + yy;
    float q[64];
#pragma unroll
    for (int p = 0; p < 16; p++) {
        float l0, h0, l1, h1;
        upk2(a0[p], l0, h0);
        upk2(a1[p], l1, h1);
        if (act) {
            g_y1[((b * 32 + 2 * p) * 52 + y) * 52 + x2] = l0;
            g_y1[((b * 32 + 2 * p + 1) * 52 + y) * 52 + x2] = h0;
            g_y1[((b * 32 + 2 * p) * 52 + y) * 52 + x2 + 26] = l1;
            g_y1[((b * 32 + 2 * p + 1) * 52 + y) * 52 + x2 + 26] = h1;
        }
        q[4 * p + 0] = l0 + l1;
        q[4 * p + 1] = fmaf(l0, l0, l1 * l1);
        q[4 * p + 2] = h0 + h1;
        q[4 * p + 3] = fmaf(h0, h0, h1 * h1);
    }
    int lane = t & 31, wid = t >> 5;
#pragma unroll
    for (int k = 0; k < 64; k++) {
        float x = q[k];
#pragma unroll
        for (int o = 16; o; o >>= 1) x += __shfl_down_sync(0xffffffffu, x, o);
        if (lane == 0) sRed[wid * 64 + k] = x;
    }
    __syncthreads();
    if (t < 64) {
        float tot = sRed[t] + sRed[64 + t] + sRed[128 + t] + sRed[192 + t];
        int c = 2 * (t >> 2) + ((t >> 1) & 1);
        if (t & 1) atomicAdd(&g_sq1[c], (double)tot);
        else       atomicAdd(&g_sum1[c], (double)tot);
    }
}

// ---------------- K3: conv2 (BN1 finalize+apply fused; BN2 raw stats fused) -----
// grid (4 ocg, 64 b), block 288. Double-buffered smem, one sync/ic.
__global__ __launch_bounds__(288, 2) void conv2_kernel(
    const float* __restrict__ w2, const float* __restrict__ g1,
    const float* __restrict__ b1) {
    __shared__ float sIn[2][2652];
    __shared__ __align__(16) float sWt[2][400];
    __shared__ float sS1[32], sSh1[32];
    __shared__ float sRed[9 * 32];
    int ocg = blockIdx.x, b = blockIdx.y, t = threadIdx.x;
    int x = t % 12, y = t / 12;
    if (t < 32) {
        double N = 64.0 * 2704.0;
        double m = g_sum1[t] / N;
        double var = g_sq1[t] / N - m * m;
        float sc = g1[t] * (float)(1.0 / sqrt(var + (double)EPS));
        sS1[t] = sc;
        sSh1[t] = b1[t] - (float)m * sc;
    }
    __syncthreads();
    // prefetch ic = 0
    {
        float s = sS1[0], sh = sSh1[0];
#pragma unroll
        for (int k = 0; k < 10; k++) {
            int i = t + k * 288;
            if (i < 2652) {
                int row = i / 52, col = i - row * 52;
                float v = 0.f;
                if (col < 51)
                    v = leaky(fmaf(g_y1[(b * 32) * 2704 + row * 52 + col], s, sh));
                sIn[0][i] = v;
            }
        }
#pragma unroll
        for (int k = 0; k < 2; k++) {
            int i = t + k * 288;
            if (i < 400) {
                int o = i & 15, kk = i >> 4;
                sWt[0][i] = w2[((ocg * 16 + o) * 32) * 25 + kk];
            }
        }
    }
    __syncthreads();
    ull a0[8], a1[8];
#pragma unroll
    for (int p = 0; p < 8; p++) { a0[p] = 0ULL; a1[p] = 0ULL; }
    for (int ic = 0; ic < 32; ic++) {
        int cur = ic & 1, nxt = cur ^ 1;
        float rIn[10], rW[2];
        if (ic < 31) {
#pragma unroll
            for (int k = 0; k < 10; k++) {
                int i = t + k * 288;
                rIn[k] = 0.f;
                if (i < 2652) {
                    int row = i / 52, col = i - row * 52;
                    if (col < 51)
                        rIn[k] = g_y1[(b * 32 + ic + 1) * 2704 + row * 52 + col];
                }
            }
#pragma unroll
            for (int k = 0; k < 2; k++) {
                int i = t + k * 288;
                if (i < 400) {
                    int o = i & 15, kk = i >> 4;
                    rW[k] = w2[((ocg * 16 + o) * 32 + ic + 1) * 25 + kk];
                }
            }
        }
#pragma unroll
        for (int ky = 0; ky < 5; ky++) {
            int rb = (2 * y + ky) * 52 + 2 * x;
#pragma unroll
            for (int kx = 0; kx < 5; kx++) {
                float v0 = sIn[cur][rb + kx], v1 = sIn[cur][rb + 24 + kx];
                ull p0 = pk2(v0, v0), p1 = pk2(v1, v1);
                const ull* wr = (const ull*)&sWt[cur][(ky * 5 + kx) * 16];
#pragma unroll
                for (int p = 0; p < 8; p++) {
                    ull w = wr[p];
                    a0[p] = fma2(p0, w, a0[p]);
                    a1[p] = fma2(p1, w, a1[p]);
                }
            }
        }
        if (ic < 31) {
            float s = sS1[ic + 1], sh = sSh1[ic + 1];
#pragma unroll
            for (int k = 0; k < 10; k++) {
                int i = t + k * 288;
                if (i < 2652) {
                    int col = i % 52;
                    sIn[nxt][i] = (col < 51) ? leaky(fmaf(rIn[k], s, sh)) : 0.f;
                }
            }
#pragma unroll
            for (int k = 0; k < 2; k++) {
                int i = t + k * 288;
                if (i < 400) sWt[nxt][i] = rW[k];
            }
        }
        __syncthreads();
    }
    // stores + fused raw stats for BN2
    float q[32];
#pragma unroll
    for (int p = 0; p < 8; p++) {
        int oc = ocg * 16 + 2 * p;
        float l0, h0, l1, h1;
        upk2(a0[p], l0, h0);
        upk2(a1[p], l1, h1);
        g_y2[(b * 64 + oc) * 576 + y * 24 + x] = l0;
        g_y2[(b * 64 + oc + 1) * 576 + y * 24 + x] = h0;
        g_y2[(b * 64 + oc) * 576 + y * 24 + x + 12] = l1;
        g_y2[(b * 64 + oc + 1) * 576 + y * 24 + x + 12] = h1;
        q[4 * p + 0] = l0 + l1;
        q[4 * p + 1] = fmaf(l0, l0, l1 * l1);
        q[4 * p + 2] = h0 + h1;
        q[4 * p + 3] = fmaf(h0, h0, h1 * h1);
    }
    int lane = t & 31, wid = t >> 5;
#pragma unroll
    for (int k = 0; k < 32; k++) {
        float v = q[k];
#pragma unroll
        for (int o = 16; o; o >>= 1) v += __shfl_down_sync(0xffffffffu, v, o);
        if (lane == 0) sRed[wid * 32 + k] = v;
    }
    __syncthreads();
    if (t < 32) {
        float tot = 0.f;
#pragma unroll
        for (int w = 0; w < 9; w++) tot += sRed[w * 32 + t];
        int c = ocg * 16 + 2 * (t >> 2) + ((t >> 1) & 1);
        if (t & 1) atomicAdd(&g_sq2[c], (double)tot);
        else       atomicAdd(&g_sum2[c], (double)tot);
    }
}

// ---------------- K4: fc1 GEMM (BN2 finalize+apply fused), split-K atomics ------
// grid (4 n-tiles of 128, 72 k-splits of 512), 256 thr, double-buffered,
// 16-wide k stages (smem: 2*(4KB+8KB) + tables = 24.8KB < 48KB).
__global__ __launch_bounds__(256, 2) void fc1_kernel(
    const float* __restrict__ W, const float* __restrict__ g2,
    const float* __restrict__ b2) {
    __shared__ __align__(16) float sX[2][16 * 64];
    __shared__ __align__(16) float sW[2][16 * 128];
    __shared__ float sS2[64], sSh2[64];
    int n0 = blockIdx.x * 128, k0 = blockIdx.y * 512, t = threadIdx.x;
    if (t < 64) {
        double N = 64.0 * 576.0;
        double m = g_sum2[t] / N;
        double var = g_sq2[t] / N - m * m;
        float sc = g2[t] * (float)(1.0 / sqrt(var + (double)EPS));
        sS2[t] = sc;
        sSh2[t] = b2[t] - (float)m * sc;
    }
    __syncthreads();
    int bgrp = t >> 5, c = t & 31, b0 = bgrp * 8;
    int xb = t >> 2, xks = (t & 3) * 4;     // X: 1 float4/thread (16x64)
    int wj = t >> 1, wks = (t & 1) * 8;     // W: 2 float4/thread (16x128)
    // prefetch stage 0
    {
        int kidx = k0 + xks;
        int ch = kidx / 576;                // 4 elems within one channel (576%4==0)
        float sc = sS2[ch], sh = sSh2[ch];
        float4 q0 = *(const float4*)&g_y2[xb * 36864 + kidx];
        float tmp[4] = {q0.x, q0.y, q0.z, q0.w};
#pragma unroll
        for (int i = 0; i < 4; i++)
            sX[0][(xks + i) * 64 + xb] = leaky(fmaf(tmp[i], sc, sh));
        const float4* ws = (const float4*)&W[(size_t)(n0 + wj) * 36864 + k0 + wks];
        float4 w0 = ws[0], w1 = ws[1];
        float tw[8] = {w0.x, w0.y, w0.z, w0.w, w1.x, w1.y, w1.z, w1.w};
#pragma unroll
        for (int i = 0; i < 8; i++) sW[0][(wks + i) * 128 + wj] = tw[i];
    }
    __syncthreads();
    ull acc[4][4];
#pragma unroll
    for (int i = 0; i < 4; i++)
#pragma unroll
        for (int j = 0; j < 4; j++) acc[i][j] = 0ULL;
    for (int kt = 0; kt < 32; kt++) {
        int cur = kt & 1, nxt = cur ^ 1;
        float xr[4], wr2[8], scn = 0.f, shn = 0.f;
        if (kt < 31) {
            int kb = k0 + (kt + 1) * 16;
            int kidx = kb + xks;
            int ch = kidx / 576;
            scn = sS2[ch];
            shn = sSh2[ch];
            float4 q0 = *(const float4*)&g_y2[xb * 36864 + kidx];
            xr[0] = q0.x; xr[1] = q0.y; xr[2] = q0.z; xr[3] = q0.w;
            const float4* ws = (const float4*)&W[(size_t)(n0 + wj) * 36864 + kb + wks];
            float4 w0 = ws[0], w1 = ws[1];
            wr2[0] = w0.x; wr2[1] = w0.y; wr2[2] = w0.z; wr2[3] = w0.w;
            wr2[4] = w1.x; wr2[5] = w1.y; wr2[6] = w1.z; wr2[7] = w1.w;
        }
#pragma unroll
        for (int kk = 0; kk < 16; kk++) {
            ull xp[4];
            const ull* xrow = (const ull*)&sX[cur][kk * 64 + b0];
#pragma unroll
            for (int bp = 0; bp < 4; bp++) xp[bp] = xrow[bp];
#pragma unroll
            for (int j = 0; j < 4; j++) {
                float w = sW[cur][kk * 128 + c + 32 * j];
                ull wp = pk2(w, w);
#pragma unroll
                for (int bp = 0; bp < 4; bp++)
                    acc[bp][j] = fma2(xp[bp], wp, acc[bp][j]);
            }
        }
        if (kt < 31) {
#pragma unroll
            for (int i = 0; i < 4; i++)
                sX[nxt][(xks + i) * 64 + xb] = leaky(fmaf(xr[i], scn, shn));
#pragma unroll
            for (int i = 0; i < 8; i++) sW[nxt][(wks + i) * 128 + wj] = wr2[i];
        }
        __syncthreads();
    }
#pragma unroll
    for (int bp = 0; bp < 4; bp++)
#pragma unroll
        for (int j = 0; j < 4; j++) {
            float l, h;
            upk2(acc[bp][j], l, h);
            int jj = n0 + c + 32 * j;
            atomicAdd(&g_fc1[(b0 + 2 * bp) * 512 + jj], l);
            atomicAdd(&g_fc1[(b0 + 2 * bp + 1) * 512 + jj], h);
        }
}

// ---------------- K5: BN3 stats ----------------
__global__ void bn3_kernel(const float* __restrict__ g3, const float* __restrict__ b3) {
    int j = threadIdx.x;   // <<<1,512>>>
    float s1 = 0.f, s2 = 0.f;
#pragma unroll 8
    for (int b = 0; b < 64; b++) {
        float v = g_fc1[b * 512 + j];
        s1 += v;
        s2 = fmaf(v, v, s2);
    }
    double m = (double)s1 / 64.0, var = (double)s2 / 64.0 - m * m;
    float sc = g3[j] * (float)(1.0 / sqrt(var + (double)EPS));
    g_s3[j] = sc;
    g_sh3[j] = b3[j] - (float)m * sc;
}

// ---------------- K6: BN3+leaky+fc2+sigmoid ----------------
__global__ void final_kernel(const float* __restrict__ w2, const float* __restrict__ b2,
                             float* __restrict__ out) {
    int b = blockIdx.x, t = threadIdx.x;   // <<<64,256>>>
    float s = 0.f;
    for (int j = t; j < 512; j += 256) {
        float v = leaky(fmaf(g_fc1[b * 512 + j], g_s3[j], g_sh3[j]));
        s += v * w2[j];
    }
    __shared__ float red[256];
    red[t] = s;
    __syncthreads();
    for (int o = 128; o > 0; o >>= 1) {
        if (t < o) red[t] += red[t + o];
        __syncthreads();
    }
    if (t == 0) {
        float z = red[0] + b2[0];
        out[b] = 1.f / (1.f + expf(-z));
    }
}

// ---------------- launch ----------------
extern "C" void kernel_launch(void* const* d_in, const int* in_sizes, int n_in,
                              void* d_out, int out_size) {
    const float* image   = (const float*)d_in[0];
    const float* conv1_w = (const float*)d_in[1];
    const float* bn1_g   = (const float*)d_in[3];
    const float* bn1_b   = (const float*)d_in[4];
    const float* conv2_w = (const float*)d_in[5];
    const float* bn2_g   = (const float*)d_in[7];
    const float* bn2_b   = (const float*)d_in[8];
    const float* fc1_w   = (const float*)d_in[9];
    const float* bn3_g   = (const float*)d_in[11];
    const float* bn3_b   = (const float*)d_in[12];
    const float* fc2_w   = (const float*)d_in[13];
    const float* fc2_b   = (const float*)d_in[14];
    float* out = (float*)d_out;

    zero_kernel<<<128, 256>>>();                                   // idx 0
    layout_kernel<<<dim3(46, 64), 256>>>(image);                   // idx 1
    conv1_kernel<<<dim3(13, 64), 128>>>(conv1_w);                  // idx 2
    conv2_kernel<<<dim3(4, 64), 288>>>(conv2_w, bn1_g, bn1_b);     // idx 3 (profiled)
    fc1_kernel<<<dim3(4, 72), 256>>>(fc1_w, bn2_g, bn2_b);         // idx 4
    bn3_kernel<<<1, 512>>>(bn3_g, bn3_b);                          // idx 5
    final_kernel<<<64, 256>>>(fc2_w, fc2_b, out);                  // idx 6
}

// round 5
// speedup vs baseline: 2.0640x; 1.0186x over previous
#include <cuda_runtime.h>
#include <math.h>

#define EPS 1e-5f
typedef unsigned long long ull;

// ---------------- persistent scratch ----------------
__device__ float g_layout[64 * 5 * 108 * 108];
__device__ float g_y1[64 * 32 * 52 * 52];
__device__ float g_y2[64 * 64 * 24 * 24];
__device__ float g_fc1[64 * 512];
__device__ float g_s3[512], g_sh3[512];
__device__ double g_sum1[32], g_sq1[32];
__device__ double g_sum2[64], g_sq2[64];

// ---------------- f32x2 helpers ----------------
__device__ __forceinline__ ull fma2(ull a, ull b, ull c) {
    ull d;
    asm("fma.rn.f32x2 %0, %1, %2, %3;" : "=l"(d) : "l"(a), "l"(b), "l"(c));
    return d;
}
__device__ __forceinline__ ull pk2(float a, float b) {
    ull r;
    asm("mov.b64 %0, {%1, %2};" : "=l"(r) : "f"(a), "f"(b));
    return r;
}
__device__ __forceinline__ void upk2(ull v, float& a, float& b) {
    asm("mov.b64 {%0, %1}, %2;" : "=f"(a), "=f"(b) : "l"(v));
}
__device__ __forceinline__ float leaky(float v) { return v > 0.f ? v : 0.2f * v; }

// ---------------- K0: layout render (+ zero fc1 acc & stats partials) ----------
__global__ void layout_kernel(const float* __restrict__ img) {
    int b = blockIdx.y, t = threadIdx.x;
    int bid = b * 46 + blockIdx.x;
    if (bid < 128) g_fc1[bid * 256 + t] = 0.f;
    if (bid == 0) {
        if (t < 32) { g_sum1[t] = 0.0; g_sq1[t] = 0.0; }
        else if (t < 96) { g_sum2[t - 32] = 0.0; g_sq2[t - 32] = 0.0; }
    }
    __shared__ float so[81];
    if (t < 81) so[t] = img[b * 81 + t];
    __syncthreads();
    int p = blockIdx.x * 256 + t;
    if (p >= 11664) return;
    int y = p / 108, x = p - y * 108;
    float fx = (float)x, fy = (float)y;
    float m[5];
#pragma unroll
    for (int c = 0; c < 5; c++) m[c] = -3.4e38f;
#pragma unroll
    for (int o = 0; o < 9; o++) {
        const float* f = &so[o * 9];
        float xc = f[0] * 108.f, yc = f[1] * 108.f;
        float hw = f[2] * 54.f, hh = f[3] * 54.f;
        float x1 = xc - hw, x2 = xc + hw, y1 = yc - hh, y2 = yc + hh;
        float x1d = fx - x1, x2d = x2 - fx, y1d = fy - y1, y2d = y2 - fy;
        float yin = __saturatef(y1d) * __saturatef(y2d);
        float xin = __saturatef(x1d) * __saturatef(x2d);
        float l1 = fmaxf(1.f - fabsf(x1d), 0.f) * yin;
        float l2 = fmaxf(1.f - fabsf(x2d), 0.f) * yin;
        float l3 = fmaxf(1.f - fabsf(y1d), 0.f) * xin;
        float l4 = fmaxf(1.f - fabsf(y2d), 0.f) * xin;
        float xym = fmaxf(fmaxf(l1, l2), fmaxf(l3, l4));
#pragma unroll
        for (int c = 0; c < 5; c++) m[c] = fmaxf(m[c], xym * f[4 + c]);
    }
#pragma unroll
    for (int c = 0; c < 5; c++) g_layout[(b * 5 + c) * 11664 + p] = m[c];
}

// ---------------- K1: conv1 + fused BN1 raw stats ----------------
// grid (13, 64), block 128 (104 active). 2 px/thread, 32 oc as 16 f32x2.
__global__ void conv1_kernel(const float* __restrict__ w1) {
    __shared__ __align__(16) float sW[4000];
    __shared__ float sIn[5 * 11 * 108];
    __shared__ float sRed[4 * 64];
    int b = blockIdx.y, tile = blockIdx.x, t = threadIdx.x;
    for (int i = t; i < 4000; i += 128) {
        int oc = i / 125, k = i - oc * 125;
        sW[k * 32 + oc] = w1[i];
    }
    int r0 = 8 * tile;
    for (int i = t; i < 5940; i += 128) {
        int ic = i / 1188, rem = i - ic * 1188;
        int row = rem / 108, col = rem - row * 108;
        sIn[i] = g_layout[(b * 5 + ic) * 11664 + (r0 + row) * 108 + col];
    }
    __syncthreads();
    bool act = (t < 104);
    int x2 = t % 26, yy = t / 26;
    ull a0[16], a1[16];
#pragma unroll
    for (int p = 0; p < 16; p++) { a0[p] = 0ULL; a1[p] = 0ULL; }
    if (act) {
        for (int ic = 0; ic < 5; ic++)
            for (int ky = 0; ky < 5; ky++) {
                int base = ic * 1188 + (2 * yy + ky) * 108 + 2 * x2;
                int kb = ic * 25 + ky * 5;
#pragma unroll
                for (int kx = 0; kx < 5; kx++) {
                    float v0 = sIn[base + kx], v1 = sIn[base + 52 + kx];
                    ull p0 = pk2(v0, v0), p1 = pk2(v1, v1);
                    const ull* wr = (const ull*)&sW[(kb + kx) * 32];
#pragma unroll
                    for (int p = 0; p < 16; p++) {
                        ull w = wr[p];
                        a0[p] = fma2(p0, w, a0[p]);
                        a1[p] = fma2(p1, w, a1[p]);
                    }
                }
            }
    }
    int y = 4 * tile + yy;
    float q[64];
#pragma unroll
    for (int p = 0; p < 16; p++) {
        float l0, h0, l1, h1;
        upk2(a0[p], l0, h0);
        upk2(a1[p], l1, h1);
        if (act) {
            g_y1[((b * 32 + 2 * p) * 52 + y) * 52 + x2] = l0;
            g_y1[((b * 32 + 2 * p + 1) * 52 + y) * 52 + x2] = h0;
            g_y1[((b * 32 + 2 * p) * 52 + y) * 52 + x2 + 26] = l1;
            g_y1[((b * 32 + 2 * p + 1) * 52 + y) * 52 + x2 + 26] = h1;
        }
        q[4 * p + 0] = l0 + l1;
        q[4 * p + 1] = fmaf(l0, l0, l1 * l1);
        q[4 * p + 2] = h0 + h1;
        q[4 * p + 3] = fmaf(h0, h0, h1 * h1);
    }
    int lane = t & 31, wid = t >> 5;
#pragma unroll
    for (int k = 0; k < 64; k++) {
        float x = q[k];
#pragma unroll
        for (int o = 16; o; o >>= 1) x += __shfl_down_sync(0xffffffffu, x, o);
        if (lane == 0) sRed[wid * 64 + k] = x;
    }
    __syncthreads();
    if (t < 64) {
        float tot = sRed[t] + sRed[64 + t] + sRed[128 + t] + sRed[192 + t];
        int c = 2 * (t >> 2) + ((t >> 1) & 1);
        if (t & 1) atomicAdd(&g_sq1[c], (double)tot);
        else       atomicAdd(&g_sum1[c], (double)tot);
    }
}

// ---------------- K2: conv2 (BN1 apply fused; BN2 raw stats fused) -----
// grid (4 ocg, 64 b), block 288. Thread tile: 4 x-consecutive px * 4 oc-pairs.
// oh = t&1 selects oc half; pxg = t>>1 selects pixel quad. Double-buffered smem.
__global__ __launch_bounds__(288, 2) void conv2_kernel(
    const float* __restrict__ w2, const float* __restrict__ g1,
    const float* __restrict__ b1) {
    __shared__ float sIn[2][2652];
    __shared__ __align__(16) float sWt[2][400];
    __shared__ float sS1[32], sSh1[32];
    __shared__ float sRed[9 * 32];
    int ocg = blockIdx.x, b = blockIdx.y, t = threadIdx.x;
    int oh = t & 1, pxg = t >> 1;
    int xg = pxg % 6, y = pxg / 6;
    int x0 = xg * 4;
    if (t < 32) {
        double N = 64.0 * 2704.0;
        double m = g_sum1[t] / N;
        double var = g_sq1[t] / N - m * m;
        float sc = g1[t] * (float)(1.0 / sqrt(var + (double)EPS));
        sS1[t] = sc;
        sSh1[t] = b1[t] - (float)m * sc;
    }
    __syncthreads();
    // prefetch ic = 0
    {
        float s = sS1[0], sh = sSh1[0];
#pragma unroll
        for (int k = 0; k < 10; k++) {
            int i = t + k * 288;
            if (i < 2652) {
                int row = i / 52, col = i - row * 52;
                float v = 0.f;
                if (col < 51)
                    v = leaky(fmaf(g_y1[(b * 32) * 2704 + row * 52 + col], s, sh));
                sIn[0][i] = v;
            }
        }
#pragma unroll
        for (int k = 0; k < 2; k++) {
            int i = t + k * 288;
            if (i < 400) {
                int o = i & 15, kk = i >> 4;
                sWt[0][i] = w2[((ocg * 16 + o) * 32) * 25 + kk];
            }
        }
    }
    __syncthreads();
    ull acc[4][4];
#pragma unroll
    for (int p = 0; p < 4; p++)
#pragma unroll
        for (int j = 0; j < 4; j++) acc[p][j] = 0ULL;
    for (int ic = 0; ic < 32; ic++) {
        int cur = ic & 1, nxt = cur ^ 1;
        float rIn[10], rW[2];
        if (ic < 31) {
#pragma unroll
            for (int k = 0; k < 10; k++) {
                int i = t + k * 288;
                rIn[k] = 0.f;
                if (i < 2652) {
                    int row = i / 52, col = i - row * 52;
                    if (col < 51)
                        rIn[k] = g_y1[(b * 32 + ic + 1) * 2704 + row * 52 + col];
                }
            }
#pragma unroll
            for (int k = 0; k < 2; k++) {
                int i = t + k * 288;
                if (i < 400) {
                    int o = i & 15, kk = i >> 4;
                    rW[k] = w2[((ocg * 16 + o) * 32 + ic + 1) * 25 + kk];
                }
            }
        }
#pragma unroll
        for (int ky = 0; ky < 5; ky++) {
            const float4* rp =
                (const float4*)&sIn[cur][(2 * y + ky) * 52 + 2 * x0];
            float4 q0 = rp[0], q1 = rp[1], q2 = rp[2];
            float in[12] = {q0.x, q0.y, q0.z, q0.w, q1.x, q1.y, q1.z, q1.w,
                            q2.x, q2.y, q2.z, q2.w};
            ull vp[11];
#pragma unroll
            for (int i = 0; i < 11; i++) vp[i] = pk2(in[i], in[i]);
#pragma unroll
            for (int kx = 0; kx < 5; kx++) {
                const ull* wr =
                    (const ull*)&sWt[cur][(ky * 5 + kx) * 16] + oh * 4;
                ull w0 = wr[0], w1 = wr[1], w2v = wr[2], w3 = wr[3];
#pragma unroll
                for (int p = 0; p < 4; p++) {
                    ull v = vp[2 * p + kx];
                    acc[p][0] = fma2(v, w0, acc[p][0]);
                    acc[p][1] = fma2(v, w1, acc[p][1]);
                    acc[p][2] = fma2(v, w2v, acc[p][2]);
                    acc[p][3] = fma2(v, w3, acc[p][3]);
                }
            }
        }
        if (ic < 31) {
            float s = sS1[ic + 1], sh = sSh1[ic + 1];
#pragma unroll
            for (int k = 0; k < 10; k++) {
                int i = t + k * 288;
                if (i < 2652) {
                    int col = i % 52;
                    sIn[nxt][i] = (col < 51) ? leaky(fmaf(rIn[k], s, sh)) : 0.f;
                }
            }
#pragma unroll
            for (int k = 0; k < 2; k++) {
                int i = t + k * 288;
                if (i < 400) sWt[nxt][i] = rW[k];
            }
        }
        __syncthreads();
    }
    // epilogue: unpack, vectorized stores, fused raw stats for BN2
    float lo[4][4], hi[4][4];
#pragma unroll
    for (int p = 0; p < 4; p++)
#pragma unroll
        for (int j = 0; j < 4; j++) upk2(acc[p][j], lo[p][j], hi[p][j]);
    float q[16];
#pragma unroll
    for (int j = 0; j < 4; j++) {
        int oc = ocg * 16 + oh * 8 + 2 * j;
        float4 vlo = make_float4(lo[0][j], lo[1][j], lo[2][j], lo[3][j]);
        float4 vhi = make_float4(hi[0][j], hi[1][j], hi[2][j], hi[3][j]);
        *(float4*)&g_y2[(b * 64 + oc) * 576 + y * 24 + x0] = vlo;
        *(float4*)&g_y2[(b * 64 + oc + 1) * 576 + y * 24 + x0] = vhi;
        q[4 * j + 0] = vlo.x + vlo.y + vlo.z + vlo.w;
        q[4 * j + 1] = fmaf(vlo.x, vlo.x, fmaf(vlo.y, vlo.y,
                       fmaf(vlo.z, vlo.z, vlo.w * vlo.w)));
        q[4 * j + 2] = vhi.x + vhi.y + vhi.z + vhi.w;
        q[4 * j + 3] = fmaf(vhi.x, vhi.x, fmaf(vhi.y, vhi.y,
                       fmaf(vhi.z, vhi.z, vhi.w * vhi.w)));
    }
    int lane = t & 31, wid = t >> 5;
#pragma unroll
    for (int k = 0; k < 16; k++) {
        float v = q[k];
#pragma unroll
        for (int o = 16; o >= 2; o >>= 1) v += __shfl_down_sync(0xffffffffu, v, o);
        if (lane < 2) sRed[wid * 32 + lane * 16 + k] = v;   // lane == oh
    }
    __syncthreads();
    if (t < 32) {
        float tot = 0.f;
#pragma unroll
        for (int w = 0; w < 9; w++) tot += sRed[w * 32 + t];
        int ohh = t >> 4, k = t & 15;
        int oc = ocg * 16 + ohh * 8 + 2 * (k >> 2) + ((k >> 1) & 1);
        if (k & 1) atomicAdd(&g_sq2[oc], (double)tot);
        else       atomicAdd(&g_sum2[oc], (double)tot);
    }
}

// ---------------- K3: fc1 GEMM (BN2 finalize+apply fused), split-K atomics ------
// grid (4 n-tiles of 128, 72 k-splits of 512), 256 thr, double-buffered 16-wide.
__global__ __launch_bounds__(256, 2) void fc1_kernel(
    const float* __restrict__ W, const float* __restrict__ g2,
    const float* __restrict__ b2) {
    __shared__ __align__(16) float sX[2][16 * 64];
    __shared__ __align__(16) float sW[2][16 * 128];
    __shared__ float sS2[64], sSh2[64];
    int n0 = blockIdx.x * 128, k0 = blockIdx.y * 512, t = threadIdx.x;
    if (t < 64) {
        double N = 64.0 * 576.0;
        double m = g_sum2[t] / N;
        double var = g_sq2[t] / N - m * m;
        float sc = g2[t] * (float)(1.0 / sqrt(var + (double)EPS));
        sS2[t] = sc;
        sSh2[t] = b2[t] - (float)m * sc;
    }
    __syncthreads();
    int bgrp = t >> 5, c = t & 31, b0 = bgrp * 8;
    int xb = t >> 2, xks = (t & 3) * 4;
    int wj = t >> 1, wks = (t & 1) * 8;
    {
        int kidx = k0 + xks;
        int ch = kidx / 576;
        float sc = sS2[ch], sh = sSh2[ch];
        float4 q0 = *(const float4*)&g_y2[xb * 36864 + kidx];
        float tmp[4] = {q0.x, q0.y, q0.z, q0.w};
#pragma unroll
        for (int i = 0; i < 4; i++)
            sX[0][(xks + i) * 64 + xb] = leaky(fmaf(tmp[i], sc, sh));
        const float4* ws = (const float4*)&W[(size_t)(n0 + wj) * 36864 + k0 + wks];
        float4 w0 = ws[0], w1 = ws[1];
        float tw[8] = {w0.x, w0.y, w0.z, w0.w, w1.x, w1.y, w1.z, w1.w};
#pragma unroll
        for (int i = 0; i < 8; i++) sW[0][(wks + i) * 128 + wj] = tw[i];
    }
    __syncthreads();
    ull acc[4][4];
#pragma unroll
    for (int i = 0; i < 4; i++)
#pragma unroll
        for (int j = 0; j < 4; j++) acc[i][j] = 0ULL;
    for (int kt = 0; kt < 32; kt++) {
        int cur = kt & 1, nxt = cur ^ 1;
        float xr[4], wr2[8], scn = 0.f, shn = 0.f;
        if (kt < 31) {
            int kb = k0 + (kt + 1) * 16;
            int kidx = kb + xks;
            int ch = kidx / 576;
            scn = sS2[ch];
            shn = sSh2[ch];
            float4 q0 = *(const float4*)&g_y2[xb * 36864 + kidx];
            xr[0] = q0.x; xr[1] = q0.y; xr[2] = q0.z; xr[3] = q0.w;
            const float4* ws = (const float4*)&W[(size_t)(n0 + wj) * 36864 + kb + wks];
            float4 w0 = ws[0], w1 = ws[1];
            wr2[0] = w0.x; wr2[1] = w0.y; wr2[2] = w0.z; wr2[3] = w0.w;
            wr2[4] = w1.x; wr2[5] = w1.y; wr2[6] = w1.z; wr2[7] = w1.w;
        }
#pragma unroll
        for (int kk = 0; kk < 16; kk++) {
            ull xp[4];
            const ull* xrow = (const ull*)&sX[cur][kk * 64 + b0];
#pragma unroll
            for (int bp = 0; bp < 4; bp++) xp[bp] = xrow[bp];
#pragma unroll
            for (int j = 0; j < 4; j++) {
                float w = sW[cur][kk * 128 + c + 32 * j];
                ull wp = pk2(w, w);
#pragma unroll
                for (int bp = 0; bp < 4; bp++)
                    acc[bp][j] = fma2(xp[bp], wp, acc[bp][j]);
            }
        }
        if (kt < 31) {
#pragma unroll
            for (int i = 0; i < 4; i++)
                sX[nxt][(xks + i) * 64 + xb] = leaky(fmaf(xr[i], scn, shn));
#pragma unroll
            for (int i = 0; i < 8; i++) sW[nxt][(wks + i) * 128 + wj] = wr2[i];
        }
        __syncthreads();
    }
#pragma unroll
    for (int bp = 0; bp < 4; bp++)
#pragma unroll
        for (int j = 0; j < 4; j++) {
            float l, h;
            upk2(acc[bp][j], l, h);
            int jj = n0 + c + 32 * j;
            atomicAdd(&g_fc1[(b0 + 2 * bp) * 512 + jj], l);
            atomicAdd(&g_fc1[(b0 + 2 * bp + 1) * 512 + jj], h);
        }
}

// ---------------- K4: BN3 stats ----------------
__global__ void bn3_kernel(const float* __restrict__ g3, const float* __restrict__ b3) {
    int j = threadIdx.x;   // <<<1,512>>>
    float s1 = 0.f, s2 = 0.f;
#pragma unroll 8
    for (int b = 0; b < 64; b++) {
        float v = g_fc1[b * 512 + j];
        s1 += v;
        s2 = fmaf(v, v, s2);
    }
    double m = (double)s1 / 64.0, var = (double)s2 / 64.0 - m * m;
    float sc = g3[j] * (float)(1.0 / sqrt(var + (double)EPS));
    g_s3[j] = sc;
    g_sh3[j] = b3[j] - (float)m * sc;
}

// ---------------- K5: BN3+leaky+fc2+sigmoid ----------------
__global__ void final_kernel(const float* __restrict__ w2, const float* __restrict__ b2,
                             float* __restrict__ out) {
    int b = blockIdx.x, t = threadIdx.x;   // <<<64,256>>>
    float s = 0.f;
    for (int j = t; j < 512; j += 256) {
        float v = leaky(fmaf(g_fc1[b * 512 + j], g_s3[j], g_sh3[j]));
        s += v * w2[j];
    }
    __shared__ float red[256];
    red[t] = s;
    __syncthreads();
    for (int o = 128; o > 0; o >>= 1) {
        if (t < o) red[t] += red[t + o];
        __syncthreads();
    }
    if (t == 0) {
        float z = red[0] + b2[0];
        out[b] = 1.f / (1.f + expf(-z));
    }
}

// ---------------- launch ----------------
extern "C" void kernel_launch(void* const* d_in, const int* in_sizes, int n_in,
                              void* d_out, int out_size) {
    const float* image   = (const float*)d_in[0];
    const float* conv1_w = (const float*)d_in[1];
    const float* bn1_g   = (const float*)d_in[3];
    const float* bn1_b   = (const float*)d_in[4];
    const float* conv2_w = (const float*)d_in[5];
    const float* bn2_g   = (const float*)d_in[7];
    const float* bn2_b   = (const float*)d_in[8];
    const float* fc1_w   = (const float*)d_in[9];
    const float* bn3_g   = (const float*)d_in[11];
    const float* bn3_b   = (const float*)d_in[12];
    const float* fc2_w   = (const float*)d_in[13];
    const float* fc2_b   = (const float*)d_in[14];
    float* out = (float*)d_out;

    layout_kernel<<<dim3(46, 64), 256>>>(image);                   // idx 0
    conv1_kernel<<<dim3(13, 64), 128>>>(conv1_w);                  // idx 1
    conv2_kernel<<<dim3(4, 64), 288>>>(conv2_w, bn1_g, bn1_b);     // idx 2
    fc1_kernel<<<dim3(4, 72), 256>>>(fc1_w, bn2_g, bn2_b);         // idx 3 (profiled)
    bn3_kernel<<<1, 512>>>(bn3_g, bn3_b);                          // idx 4
    final_kernel<<<64, 256>>>(fc2_w, fc2_b, out);                  // idx 5
}